// round 15
// baseline (speedup 1.0000x reference)
#include <cuda_runtime.h>
#include <cuda_bf16.h>
#include <math.h>
#include <stdint.h>

#define Hh 128
#define Ww 128
#define Nn (Hh*Ww)
#define Cc 64
#define TT 64
#define TILES (Nn/TT)
#define PB 64
#define BMAX 16

__device__ float g_part_kv[BMAX*PB*1024];
__device__ float g_part_ks[BMAX*PB*64];
__device__ float g_kvn[BMAX*1024];
__device__ float g_kmean[BMAX*64];
__device__ float2 g_cs[2048];

#define LN1E4_OVER16 0.57564627324851145f

__device__ __forceinline__ float elu1(float v) { return v > 0.f ? v + 1.f : __expf(v); }
__device__ __forceinline__ void bf_split(float a, float b, uint32_t& hi, uint32_t& lo) {
    __nv_bfloat162 h(__float2bfloat16(a), __float2bfloat16(b));
    hi = *(uint32_t*)&h;
    __nv_bfloat162 l(__float2bfloat16(a - __bfloat162float(h.x)),
                     __float2bfloat16(b - __bfloat162float(h.y)));
    lo = *(uint32_t*)&l;
}
__device__ __forceinline__ void mma_bf16(float* c, uint32_t a0, uint32_t a1, uint32_t a2,
                                         uint32_t a3, uint32_t b0, uint32_t b1) {
    asm volatile("mma.sync.aligned.m16n8k16.row.col.f32.bf16.bf16.f32 "
                 "{%0,%1,%2,%3}, {%4,%5,%6,%7}, {%8,%9}, {%0,%1,%2,%3};"
                 : "+f"(c[0]), "+f"(c[1]), "+f"(c[2]), "+f"(c[3])
                 : "r"(a0), "r"(a1), "r"(a2), "r"(a3), "r"(b0), "r"(b1));
}
__device__ __forceinline__ void ldsm4(uint32_t addr, uint32_t& r0, uint32_t& r1,
                                      uint32_t& r2, uint32_t& r3) {
    asm volatile("ldmatrix.sync.aligned.m8n8.x4.shared.b16 {%0,%1,%2,%3}, [%4];"
                 : "=r"(r0), "=r"(r1), "=r"(r2), "=r"(r3) : "r"(addr));
}
__device__ __forceinline__ void ldsm4t(uint32_t addr, uint32_t& r0, uint32_t& r1,
                                       uint32_t& r2, uint32_t& r3) {
    asm volatile("ldmatrix.sync.aligned.m8n8.x4.trans.shared.b16 {%0,%1,%2,%3}, [%4];"
                 : "=r"(r0), "=r"(r1), "=r"(r2), "=r"(r3) : "r"(addr));
}
__device__ __forceinline__ void ldsm2t(uint32_t addr, uint32_t& r0, uint32_t& r1) {
    asm volatile("ldmatrix.sync.aligned.m8n8.x2.trans.shared.b16 {%0,%1}, [%2];"
                 : "=r"(r0), "=r"(r1) : "r"(addr));
}
__device__ __forceinline__ uint32_t smem_u32(const void* p) {
    uint32_t a;
    asm("{ .reg .u64 t; cvta.to.shared.u64 t, %1; cvt.u32.u64 %0, t; }" : "=r"(a) : "l"(p));
    return a;
}

__global__ void init_tables() {
    int idx = threadIdx.x + blockIdx.x * 256;
    if (idx < 2048) {
        int pos = idx >> 4, k = idx & 15;
        float theta = expf(-(float)k * LN1E4_OVER16);
        g_cs[idx] = make_float2(cosf((float)pos * theta), sinf((float)pos * theta));
    }
}

// ===========================================================================
// k_pass_mma v2: GEMM1 via HMMA + kv accumulation via HMMA (ldmatrix.trans).
// smem u32: W_HI 0 | W_LO 2304 | A_HI 4608 | A_LO 6912 | KS_HI 9216 | KS_LO 11520
// total 13824 u32 = 55296 B. ksum red overlays KS region at the end.
// ===========================================================================
#define KW_HI 0
#define KW_LO 2304
#define KA_HI 4608
#define KA_LO 6912
#define KS_HI 9216
#define KS_LO 11520
#define SMEM_K2 (13824 * 4)

__global__ __launch_bounds__(256, 4) void k_pass_mma(const float* __restrict__ x,
                                                     const float* __restrict__ qkw,
                                                     const float* __restrict__ qkb) {
    extern __shared__ float sm[];
    uint32_t* su = (uint32_t*)sm;
    const uint32_t smb = smem_u32(sm);

    const int b = blockIdx.y, pb = blockIdx.x, tid = threadIdx.x;
    const int wid = tid >> 5, lid = tid & 31;
    const int g = lid >> 2, t4 = lid & 3;
    const int wm = wid & 3, wn = wid >> 2;
    const float* xb = x + (size_t)b * Nn * Cc;

    // stage W (k weights rows 64..127) bf16 hi/lo, stride 36 words
#pragma unroll
    for (int k = 0; k < 4; k++) {
        int idx = tid + k * 256;
        int f = idx >> 4, c4 = idx & 15;
        float4 w = *(const float4*)(qkw + (size_t)(64 + f) * 64 + c4 * 4);
        uint32_t h0, l0, h1, l1;
        bf_split(w.x, w.y, h0, l0);
        bf_split(w.z, w.w, h1, l1);
        int o = f * 36 + c4 * 2;
        *(uint2*)&su[KW_HI + o] = make_uint2(h0, h1);
        *(uint2*)&su[KW_LO + o] = make_uint2(l0, l1);
    }

    // GEMM1 ldmatrix addressing
    const int Ml = lid >> 3;
    const uint32_t awordb = (uint32_t)((wm * 16 + (lid & 7) + ((lid >> 3) & 1) * 8) * 36
                                       + ((lid >> 4) & 1) * 4);
    const uint32_t bwordb = (uint32_t)((wn * 32 + (Ml >> 1) * 8 + (lid & 7)) * 36 + (Ml & 1) * 4);

    // kv MMA: warp owns (head hd, e-half eh)
    const int hd = wid >> 1, eh = wid & 1;
    const uint32_t kva_row = (uint32_t)((lid & 7) + ((lid >> 4) & 1) * 8);     // + kstep*16
    const uint32_t kva_col = (uint32_t)(hd * 8 + ((lid >> 3) & 1) * 4);
    const uint32_t kvb_row = (uint32_t)((lid & 7) + ((lid >> 3) & 1) * 8);     // + kstep*16
    const uint32_t kvb_col = (uint32_t)(hd * 8 + eh * 4);
    float kvc[4] = {0.f, 0.f, 0.f, 0.f};
    float ksum8[8] = {};

    for (int tile = pb; tile < TILES; tile += PB) {
        const int token0 = tile * TT;
        __syncthreads();   // prior kv MMA reads of KA/KS done

        // stage x tile as bf16 hi/lo only
#pragma unroll
        for (int k = 0; k < 4; k++) {
            int idx = tid + k * 256;
            int t = idx >> 4, c4 = idx & 15;
            float4 v = *(const float4*)(xb + (size_t)(token0 + t) * Cc + c4 * 4);
            uint32_t h0, l0, h1, l1;
            bf_split(v.x, v.y, h0, l0);
            bf_split(v.z, v.w, h1, l1);
            int o = t * 36 + c4 * 2;
            *(uint2*)&su[KA_HI + o] = make_uint2(h0, h1);
            *(uint2*)&su[KA_LO + o] = make_uint2(l0, l1);
        }
        __syncthreads();

        // GEMM1: k = x @ Wk^T (hi/lo 3-term)
        float acc[4][4] = {};
#pragma unroll
        for (int term = 0; term < 3; term++) {
            const uint32_t Aoff = smb + ((term == 2) ? KA_LO : KA_HI) * 4;
            const uint32_t Boff = smb + ((term == 1) ? KW_LO : KW_HI) * 4;
#pragma unroll
            for (int kt = 0; kt < 4; kt++) {
                uint32_t a0, a1, a2, a3;
                ldsm4(Aoff + (awordb + kt * 8) * 4, a0, a1, a2, a3);
#pragma unroll
                for (int p = 0; p < 2; p++) {
                    uint32_t b00, b01, b10, b11;
                    ldsm4(Boff + (bwordb + p * 16 * 36 + kt * 8) * 4, b00, b01, b10, b11);
                    mma_bf16(acc[2 * p], a0, a1, a2, a3, b00, b01);
                    mma_bf16(acc[2 * p + 1], a0, a1, a2, a3, b10, b11);
                }
            }
        }

        // epilogue: bias+elu, ksum, rope -> KS_HI/KS_LO as bf16 [t][d]
#pragma unroll
        for (int half = 0; half < 2; half++) {
            int r = wm * 16 + g + half * 8;
            int token = token0 + r;
            int pos = (wn == 0) ? (token >> 7) : (token & 127);
#pragma unroll
            for (int nt = 0; nt < 4; nt++) {
                int n = wn * 32 + nt * 8 + t4 * 2;
                float k0 = elu1(acc[nt][half * 2 + 0] + __ldg(qkb + 64 + n));
                float k1 = elu1(acc[nt][half * 2 + 1] + __ldg(qkb + 64 + n + 1));
                ksum8[nt * 2] += k0; ksum8[nt * 2 + 1] += k1;
                float2 cs = __ldg(&g_cs[pos * 16 + nt * 4 + t4]);
                float ox = k0 * cs.x - k1 * cs.y;
                float oy = k0 * cs.y + k1 * cs.x;
                uint32_t h, l;
                bf_split(ox, oy, h, l);
                su[KS_HI + r * 36 + (n >> 1)] = h;
                su[KS_LO + r * 36 + (n >> 1)] = l;
            }
        }
        __syncthreads();   // KS writes visible to all warps

        // kv MMA: C(16x8) += k_rope^T(16x64) @ v(64x8), 3-term hi/lo
#pragma unroll
        for (int kt = 0; kt < 4; kt++) {
            uint32_t base = (uint32_t)(kt * 16);
            uint32_t ah0, ah1, ah2, ah3, al0, al1, al2, al3;
            ldsm4t(smb + (KS_HI + (base + kva_row) * 36 + kva_col) * 4, ah0, ah1, ah2, ah3);
            ldsm4t(smb + (KS_LO + (base + kva_row) * 36 + kva_col) * 4, al0, al1, al2, al3);
            uint32_t bh0, bh1, bl0, bl1;
            ldsm2t(smb + (KA_HI + (base + kvb_row) * 36 + kvb_col) * 4, bh0, bh1);
            ldsm2t(smb + (KA_LO + (base + kvb_row) * 36 + kvb_col) * 4, bl0, bl1);
            mma_bf16(kvc, ah0, ah1, ah2, ah3, bh0, bh1);
            mma_bf16(kvc, ah0, ah1, ah2, ah3, bl0, bl1);
            mma_bf16(kvc, al0, al1, al2, al3, bh0, bh1);
        }
    }

    __syncthreads();
    // kv fragment write (warp-exclusive -> deterministic, no smem reduction)
    {
        float* pkv = g_part_kv + ((size_t)(b * PB + pb)) * 1024;
        int e0 = eh * 8 + 2 * t4;
        *(float2*)&pkv[hd * 256 + g * 16 + e0]       = make_float2(kvc[0], kvc[1]);
        *(float2*)&pkv[hd * 256 + (g + 8) * 16 + e0] = make_float2(kvc[2], kvc[3]);
    }

    // ksum reduction (reuse KS region as float scratch)
    float* red = sm + KS_HI;   // 2048 floats used
#pragma unroll
    for (int j = 0; j < 8; j++) {
        int c = wn * 32 + (j >> 1) * 8 + t4 * 2 + (j & 1);
        red[c * 32 + wm * 8 + g] = ksum8[j];
    }
    __syncthreads();
    if (tid < 64) {
        float s = 0.f;
#pragma unroll
        for (int i = 0; i < 32; i++) s += red[tid * 32 + i];
        g_part_ks[(size_t)(b * PB + pb) * 64 + tid] = s;
    }
}

__global__ __launch_bounds__(256) void reduce_pass() {
    const int b = blockIdx.x, tid = threadIdx.x;
    const float invN = 1.0f / (float)Nn;
    for (int e = tid; e < 1024; e += 256) {
        float s = 0.f;
        for (int p = 0; p < PB; p++) s += g_part_kv[(size_t)(b * PB + p) * 1024 + e];
        g_kvn[b * 1024 + e] = s * invN;
    }
    if (tid < 64) {
        float s = 0.f;
        for (int p = 0; p < PB; p++) s += g_part_ks[(size_t)(b * PB + p) * 64 + tid];
        g_kmean[b * 64 + tid] = s * invN;
    }
}

// ===========================================================================
// q_pass_mma (unchanged from R14: GEMM1 ldmatrix + fused GEMM2)
// ===========================================================================
#define UA_HI 0
#define UA_LO 2304
#define UB_HI 4608
#define UB_LO 6912
#define FSKV  9216
#define FSKM  10240
#define FSKB  10304
#define SMEM_Q (10368 * 4)
#define AST 66

__global__ __launch_bounds__(256, 4) void q_pass_mma(const float* __restrict__ x,
                                                     const float* __restrict__ qkw,
                                                     const float* __restrict__ qkb,
                                                     const float* __restrict__ lw,
                                                     const float* __restrict__ lb,
                                                     float* __restrict__ out) {
    extern __shared__ float sm[];
    uint32_t* su = (uint32_t*)sm;
    float* abuf  = sm;
    float* slepe = sm + 64 * AST;
    float* skv   = sm + FSKV;
    float* skm   = sm + FSKM;
    float* skb   = sm + FSKB;
    const uint32_t smb = smem_u32(sm);

    const int b = blockIdx.y, tile = blockIdx.x, tid = threadIdx.x;
    const int wid = tid >> 5, lid = tid & 31;
    const int token0 = tile * TT;
    const float* xb = x + (size_t)b * Nn * Cc;

#pragma unroll
    for (int k = 0; k < 4; k++) {
        int idx = tid + k * 256;
        int t = idx >> 4, c4 = idx & 15;
        float4 v = *(const float4*)(xb + (size_t)(token0 + t) * Cc + c4 * 4);
        uint32_t h0, l0, h1, l1;
        bf_split(v.x, v.y, h0, l0);
        bf_split(v.z, v.w, h1, l1);
        int o = t * 36 + c4 * 2;
        *(uint2*)&su[UA_HI + o] = make_uint2(h0, h1);
        *(uint2*)&su[UA_LO + o] = make_uint2(l0, l1);
        float4 w = *(const float4*)(qkw + (size_t)t * 64 + c4 * 4);
        bf_split(w.x, w.y, h0, l0);
        bf_split(w.z, w.w, h1, l1);
        *(uint2*)&su[UB_HI + o] = make_uint2(h0, h1);
        *(uint2*)&su[UB_LO + o] = make_uint2(l0, l1);
    }
    for (int i = tid; i < 1024; i += 256) skv[i] = g_kvn[b * 1024 + i];
    if (tid < 64) skm[tid] = g_kmean[b * 64 + tid];
    if (tid >= 64 && tid < 128) skb[tid - 64] = qkb[tid - 64];
    __syncthreads();

    const int g = lid >> 2, t4 = lid & 3;
    const int wm = wid & 3, wn = wid >> 2;
    const int Ml = lid >> 3;
    const uint32_t awordb = (uint32_t)((wm * 16 + (lid & 7) + ((lid >> 3) & 1) * 8) * 36
                                       + ((lid >> 4) & 1) * 4);
    const uint32_t bwordb = (uint32_t)((wn * 32 + (Ml >> 1) * 8 + (lid & 7)) * 36 + (Ml & 1) * 4);

    float acc[4][4] = {};
#pragma unroll
    for (int term = 0; term < 3; term++) {
        const uint32_t Aoff = smb + ((term == 2) ? UA_LO : UA_HI) * 4;
        const uint32_t Boff = smb + ((term == 1) ? UB_LO : UB_HI) * 4;
#pragma unroll
        for (int kt = 0; kt < 4; kt++) {
            uint32_t a0, a1, a2, a3;
            ldsm4(Aoff + (awordb + kt * 8) * 4, a0, a1, a2, a3);
#pragma unroll
            for (int p = 0; p < 2; p++) {
                uint32_t b00, b01, b10, b11;
                ldsm4(Boff + (bwordb + p * 16 * 36 + kt * 8) * 4, b00, b01, b10, b11);
                mma_bf16(acc[2 * p], a0, a1, a2, a3, b00, b01);
                mma_bf16(acc[2 * p + 1], a0, a1, a2, a3, b10, b11);
            }
        }
    }

    uint32_t afh[2][4], afl[2][4];
#pragma unroll
    for (int half = 0; half < 2; half++) {
        int r = wm * 16 + g + half * 8;
        int token = token0 + r;
        float q[8];
        float zp0 = 0.f, zp1 = 0.f;
#pragma unroll
        for (int nt = 0; nt < 4; nt++) {
            int n = wn * 32 + nt * 8 + t4 * 2;
            float q0 = elu1(acc[nt][half * 2 + 0] + skb[n]);
            float q1 = elu1(acc[nt][half * 2 + 1] + skb[n + 1]);
            float zc = q0 * skm[n] + q1 * skm[n + 1];
            if (nt < 2) zp0 += zc; else zp1 += zc;
            q[nt * 2] = q0; q[nt * 2 + 1] = q1;
        }
        zp0 += __shfl_xor_sync(0xffffffffu, zp0, 1);
        zp0 += __shfl_xor_sync(0xffffffffu, zp0, 2);
        zp1 += __shfl_xor_sync(0xffffffffu, zp1, 1);
        zp1 += __shfl_xor_sync(0xffffffffu, zp1, 2);
        float z0 = 1.0f / (zp0 + 1e-6f), z1 = 1.0f / (zp1 + 1e-6f);
        int pos = (wn == 0) ? (token >> 7) : (token & 127);
#pragma unroll
        for (int nt = 0; nt < 4; nt++) {
            float2 cs = __ldg(&g_cs[pos * 16 + nt * 4 + t4]);
            float zz = (nt < 2) ? z0 : z1;
            float ox = (q[2 * nt] * cs.x - q[2 * nt + 1] * cs.y) * zz;
            float oy = (q[2 * nt] * cs.y + q[2 * nt + 1] * cs.x) * zz;
            int hh2 = nt >> 1, slot = (nt & 1) * 2 + half;
            bf_split(ox, oy, afh[hh2][slot], afl[hh2][slot]);
        }
    }
    __syncthreads();

#pragma unroll
    for (int hh2 = 0; hh2 < 2; hh2++) {
        int head = wn * 2 + hh2;
        const float* kvh = skv + head * 256 + g;
#pragma unroll
        for (int nh = 0; nh < 2; nh++) {
            const float* kb = kvh + nh * 8;
            float f00 = kb[(2 * t4) * 16],     f01 = kb[(2 * t4 + 1) * 16];
            float f10 = kb[(2 * t4 + 8) * 16], f11 = kb[(2 * t4 + 9) * 16];
            uint32_t bh0, bl0, bh1, bl1;
            bf_split(f00, f01, bh0, bl0);
            bf_split(f10, f11, bh1, bl1);
            float c[4] = {0.f, 0.f, 0.f, 0.f};
            mma_bf16(c, afh[hh2][0], afh[hh2][1], afh[hh2][2], afh[hh2][3], bh0, bh1);
            mma_bf16(c, afh[hh2][0], afh[hh2][1], afh[hh2][2], afh[hh2][3], bl0, bl1);
            mma_bf16(c, afl[hh2][0], afl[hh2][1], afl[hh2][2], afl[hh2][3], bh0, bh1);
            int col = head * 16 + nh * 8 + 2 * t4;
            int r0 = wm * 16 + g;
            *(float2*)&abuf[r0 * AST + col]       = make_float2(c[0], c[1]);
            *(float2*)&abuf[(r0 + 8) * AST + col] = make_float2(c[2], c[3]);
        }
    }

    {
        int ch = tid & 63, tg = tid >> 6;
        float w9[9];
#pragma unroll
        for (int k = 0; k < 9; k++) w9[k] = lw[ch * 9 + k];
        float biasl = lb[ch];
        const int hh = token0 >> 7;
        const int ww0 = token0 & 127;
        const int wstart = ww0 + tg * 16;
        const bool hm = hh > 0, hp = hh < (Hh - 1);
        const float* rm = xb + ((size_t)(hh - 1) * Ww) * Cc + ch;
        const float* r0p = xb + ((size_t)hh * Ww) * Cc + ch;
        const float* rp = xb + ((size_t)(hh + 1) * Ww) * Cc + ch;
        float La, Lb2, Lc, Ma, Mb2, Mc, Ra, Rb2, Rc;
        {
            int gw = wstart - 1;
            if ((unsigned)gw < (unsigned)Ww) {
                La = hm ? rm[(size_t)gw * Cc] : 0.f;
                Lb2 = r0p[(size_t)gw * Cc];
                Lc = hp ? rp[(size_t)gw * Cc] : 0.f;
            } else { La = Lb2 = Lc = 0.f; }
            gw = wstart;
            Ma = hm ? rm[(size_t)gw * Cc] : 0.f;
            Mb2 = r0p[(size_t)gw * Cc];
            Mc = hp ? rp[(size_t)gw * Cc] : 0.f;
        }
#pragma unroll
        for (int j = 0; j < 16; j++) {
            int gw = wstart + j + 1;
            if ((unsigned)gw < (unsigned)Ww) {
                Ra = hm ? rm[(size_t)gw * Cc] : 0.f;
                Rb2 = r0p[(size_t)gw * Cc];
                Rc = hp ? rp[(size_t)gw * Cc] : 0.f;
            } else { Ra = Rb2 = Rc = 0.f; }
            float s = biasl;
            s = fmaf(w9[0], La, s);  s = fmaf(w9[1], Ma, s);  s = fmaf(w9[2], Ra, s);
            s = fmaf(w9[3], Lb2, s); s = fmaf(w9[4], Mb2, s); s = fmaf(w9[5], Rb2, s);
            s = fmaf(w9[6], Lc, s);  s = fmaf(w9[7], Mc, s);  s = fmaf(w9[8], Rc, s);
            slepe[(tg * 16 + j) * AST + ch] = s;
            La = Ma; Lb2 = Mb2; Lc = Mc;
            Ma = Ra; Mb2 = Rb2; Mc = Rc;
        }
    }
    __syncthreads();

    {
        int t = tid & 63, hg = tid >> 6;
        int token = token0 + t;
        float* ob = out + (size_t)b * Cc * Nn;
#pragma unroll
        for (int j = 0; j < 16; j++) {
            int ch = hg * 16 + j;
            ob[(size_t)ch * Nn + token] = abuf[t * AST + ch] + slepe[t * AST + ch];
        }
    }
}

// ---------------------------------------------------------------------------
extern "C" void kernel_launch(void* const* d_in, const int* in_sizes, int n_in,
                              void* d_out, int out_size) {
    const float* x   = (const float*)d_in[0];
    const float* qkw = (const float*)d_in[3];
    const float* qkb = (const float*)d_in[4];
    const float* lw  = (const float*)d_in[5];
    const float* lb  = (const float*)d_in[6];
    float* out = (float*)d_out;

    int B = in_sizes[0] / (Nn * Cc);
    if (B > BMAX) B = BMAX;

    cudaFuncSetAttribute(k_pass_mma, cudaFuncAttributeMaxDynamicSharedMemorySize, SMEM_K2);
    cudaFuncSetAttribute(q_pass_mma, cudaFuncAttributeMaxDynamicSharedMemorySize, SMEM_Q);

    init_tables<<<8, 256>>>();
    k_pass_mma<<<dim3(PB, B), 256, SMEM_K2>>>(x, qkw, qkb);
    reduce_pass<<<B, 256>>>();
    q_pass_mma<<<dim3(TILES, B), 256, SMEM_Q>>>(x, qkw, qkb, lw, lb, out);
}

// round 16
// speedup vs baseline: 1.2185x; 1.2185x over previous
#include <cuda_runtime.h>
#include <cuda_bf16.h>
#include <math.h>
#include <stdint.h>

#define Hh 128
#define Ww 128
#define Nn (Hh*Ww)
#define Cc 64
#define TT 64
#define TILES (Nn/TT)
#define PB 64
#define BMAX 16

__device__ float g_part_kv[BMAX*PB*1024];
__device__ float g_part_ks[BMAX*PB*64];
__device__ float g_kvn[BMAX*1024];
__device__ float g_kmean[BMAX*64];
__device__ float2 g_cs[2048];
__device__ uint32_t g_wq_hi[2048], g_wq_lo[2048], g_wk_hi[2048], g_wk_lo[2048];

#define LN1E4_OVER16 0.57564627324851145f

__device__ __forceinline__ float elu1(float v) { return v > 0.f ? v + 1.f : __expf(v); }
__device__ __forceinline__ unsigned long long pack2(float lo, float hi) {
    unsigned long long r; asm("mov.b64 %0, {%1,%2};" : "=l"(r) : "f"(lo), "f"(hi)); return r;
}
__device__ __forceinline__ float2 unpack2(unsigned long long v) {
    float2 r; asm("mov.b64 {%0,%1}, %2;" : "=f"(r.x), "=f"(r.y) : "l"(v)); return r;
}
__device__ __forceinline__ void fma2(unsigned long long& d, unsigned long long a, unsigned long long b) {
    asm("fma.rn.f32x2 %0, %1, %2, %0;" : "+l"(d) : "l"(a), "l"(b));
}
__device__ __forceinline__ void bf_split(float a, float b, uint32_t& hi, uint32_t& lo) {
    __nv_bfloat162 h(__float2bfloat16(a), __float2bfloat16(b));
    hi = *(uint32_t*)&h;
    __nv_bfloat162 l(__float2bfloat16(a - __bfloat162float(h.x)),
                     __float2bfloat16(b - __bfloat162float(h.y)));
    lo = *(uint32_t*)&l;
}
__device__ __forceinline__ void mma_bf16(float* c, uint32_t a0, uint32_t a1, uint32_t a2,
                                         uint32_t a3, uint32_t b0, uint32_t b1) {
    asm volatile("mma.sync.aligned.m16n8k16.row.col.f32.bf16.bf16.f32 "
                 "{%0,%1,%2,%3}, {%4,%5,%6,%7}, {%8,%9}, {%0,%1,%2,%3};"
                 : "+f"(c[0]), "+f"(c[1]), "+f"(c[2]), "+f"(c[3])
                 : "r"(a0), "r"(a1), "r"(a2), "r"(a3), "r"(b0), "r"(b1));
}
__device__ __forceinline__ void ldsm4(uint32_t addr, uint32_t& r0, uint32_t& r1,
                                      uint32_t& r2, uint32_t& r3) {
    asm volatile("ldmatrix.sync.aligned.m8n8.x4.shared.b16 {%0,%1,%2,%3}, [%4];"
                 : "=r"(r0), "=r"(r1), "=r"(r2), "=r"(r3) : "r"(addr));
}
__device__ __forceinline__ uint32_t smem_u32(const void* p) {
    uint32_t a;
    asm("{ .reg .u64 t; cvta.to.shared.u64 t, %1; cvt.u32.u64 %0, t; }" : "=r"(a) : "l"(p));
    return a;
}

__global__ void init_tables(const float* __restrict__ qkw) {
    int idx = threadIdx.x + blockIdx.x * 256;
    if (idx < 2048) {
        int pos = idx >> 4, k = idx & 15;
        float theta = expf(-(float)k * LN1E4_OVER16);
        g_cs[idx] = make_float2(cosf((float)pos * theta), sinf((float)pos * theta));
    }
    if (idx < 1024) {
        int f = idx >> 4, c4 = idx & 15;
        float4 wq = *(const float4*)(qkw + (size_t)f * 64 + c4 * 4);
        float4 wk = *(const float4*)(qkw + (size_t)(64 + f) * 64 + c4 * 4);
        uint32_t h0, l0, h1, l1;
        bf_split(wq.x, wq.y, h0, l0); bf_split(wq.z, wq.w, h1, l1);
        g_wq_hi[f * 32 + c4 * 2] = h0; g_wq_hi[f * 32 + c4 * 2 + 1] = h1;
        g_wq_lo[f * 32 + c4 * 2] = l0; g_wq_lo[f * 32 + c4 * 2 + 1] = l1;
        bf_split(wk.x, wk.y, h0, l0); bf_split(wk.z, wk.w, h1, l1);
        g_wk_hi[f * 32 + c4 * 2] = h0; g_wk_hi[f * 32 + c4 * 2 + 1] = h1;
        g_wk_lo[f * 32 + c4 * 2] = l0; g_wk_lo[f * 32 + c4 * 2 + 1] = l1;
    }
}

// ---- shared GEMM1 macro body: per-kt fused 3-term hi/lo ----
#define GEMM1_BODY(AHI, ALO, BHI, BLO)                                           \
    {                                                                            \
        const uint32_t AoffH = smb + (AHI) * 4, AoffL = smb + (ALO) * 4;         \
        const uint32_t BoffH = smb + (BHI) * 4, BoffL = smb + (BLO) * 4;         \
        _Pragma("unroll")                                                        \
        for (int kt = 0; kt < 4; kt++) {                                         \
            uint32_t ah0, ah1, ah2, ah3, al0, al1, al2, al3;                     \
            ldsm4(AoffH + (awordb + kt * 8) * 4, ah0, ah1, ah2, ah3);            \
            ldsm4(AoffL + (awordb + kt * 8) * 4, al0, al1, al2, al3);            \
            _Pragma("unroll")                                                    \
            for (int p = 0; p < 2; p++) {                                        \
                uint32_t bh00, bh01, bh10, bh11, bl00, bl01, bl10, bl11;         \
                ldsm4(BoffH + (bwordb + p * 16 * 36 + kt * 8) * 4, bh00, bh01, bh10, bh11); \
                ldsm4(BoffL + (bwordb + p * 16 * 36 + kt * 8) * 4, bl00, bl01, bl10, bl11); \
                mma_bf16(acc[2 * p], ah0, ah1, ah2, ah3, bh00, bh01);            \
                mma_bf16(acc[2 * p + 1], ah0, ah1, ah2, ah3, bh10, bh11);        \
                mma_bf16(acc[2 * p], ah0, ah1, ah2, ah3, bl00, bl01);            \
                mma_bf16(acc[2 * p + 1], ah0, ah1, ah2, ah3, bl10, bl11);        \
                mma_bf16(acc[2 * p], al0, al1, al2, al3, bh00, bh01);            \
                mma_bf16(acc[2 * p + 1], al0, al1, al2, al3, bh10, bh11);        \
            }                                                                    \
        }                                                                        \
    }

// ===========================================================================
// k_pass_mma (R14 design + restructured GEMM1 + pre-split W)
// ===========================================================================
#define KW_HI 0
#define KW_LO 2304
#define KA_HI 4608
#define KA_LO 6912
#define KKS   4608
#define KXS   9216
#define SMEM_K2 (13568 * 4)

__global__ __launch_bounds__(256, 4) void k_pass_mma(const float* __restrict__ x,
                                                     const float* __restrict__ qkb) {
    extern __shared__ float sm[];
    uint32_t* su = (uint32_t*)sm;
    float (*ks)[68] = (float (*)[68])(sm + KKS);
    float (*xs)[68] = (float (*)[68])(sm + KXS);
    const uint32_t smb = smem_u32(sm);

    const int b = blockIdx.y, pb = blockIdx.x, tid = threadIdx.x;
    const int wid = tid >> 5, lid = tid & 31;
    const int g = lid >> 2, t4 = lid & 3;
    const int wm = wid & 3, wn = wid >> 2;
    const float* xb = x + (size_t)b * Nn * Cc;

    // stage pre-split W
#pragma unroll
    for (int k = 0; k < 4; k++) {
        int idx = tid + k * 256;
        int f = idx >> 4, c4 = idx & 15;
        int o = f * 36 + c4 * 2;
        *(uint2*)&su[KW_HI + o] = *(const uint2*)&g_wk_hi[f * 32 + c4 * 2];
        *(uint2*)&su[KW_LO + o] = *(const uint2*)&g_wk_lo[f * 32 + c4 * 2];
    }

    float ksum8[8] = {};
    const int e4 = (tid & 3) * 4, d4 = ((tid >> 2) & 3) * 4;
    const int q4 = (tid >> 4) & 3, hd2 = tid >> 6;
    unsigned long long kvp[4][2] = {};
    const int Ml = lid >> 3;
    const uint32_t awordb = (uint32_t)((wm * 16 + (lid & 7) + ((lid >> 3) & 1) * 8) * 36
                                       + ((lid >> 4) & 1) * 4);
    const uint32_t bwordb = (uint32_t)((wn * 32 + (Ml >> 1) * 8 + (lid & 7)) * 36 + (Ml & 1) * 4);

    for (int tile = pb; tile < TILES; tile += PB) {
        const int token0 = tile * TT;
        __syncthreads();
#pragma unroll
        for (int k = 0; k < 4; k++) {
            int idx = tid + k * 256;
            int t = idx >> 4, c4 = idx & 15;
            float4 v = *(const float4*)(xb + (size_t)(token0 + t) * Cc + c4 * 4);
            *(float4*)&xs[t][c4 * 4] = v;
            uint32_t h0, l0, h1, l1;
            bf_split(v.x, v.y, h0, l0);
            bf_split(v.z, v.w, h1, l1);
            int o = t * 36 + c4 * 2;
            *(uint2*)&su[KA_HI + o] = make_uint2(h0, h1);
            *(uint2*)&su[KA_LO + o] = make_uint2(l0, l1);
        }
        __syncthreads();

        float acc[4][4] = {};
        GEMM1_BODY(KA_HI, KA_LO, KW_HI, KW_LO)
        __syncthreads();

#pragma unroll
        for (int half = 0; half < 2; half++) {
            int r = wm * 16 + g + half * 8;
            int token = token0 + r;
            int pos = (wn == 0) ? (token >> 7) : (token & 127);
#pragma unroll
            for (int nt = 0; nt < 4; nt++) {
                int n = wn * 32 + nt * 8 + t4 * 2;
                float k0 = elu1(acc[nt][half * 2 + 0] + __ldg(qkb + 64 + n));
                float k1 = elu1(acc[nt][half * 2 + 1] + __ldg(qkb + 64 + n + 1));
                ksum8[nt * 2] += k0; ksum8[nt * 2 + 1] += k1;
                float2 cs = __ldg(&g_cs[pos * 16 + nt * 4 + t4]);
                float2 o;
                o.x = k0 * cs.x - k1 * cs.y;
                o.y = k0 * cs.y + k1 * cs.x;
                *(float2*)&ks[r][n] = o;
            }
        }
        __syncthreads();

#pragma unroll 4
        for (int t = q4 * 16; t < q4 * 16 + 16; t++) {
            ulonglong2 kk = *(const ulonglong2*)&ks[t][hd2 * 16 + d4];
            ulonglong2 vv = *(const ulonglong2*)&xs[t][hd2 * 16 + e4];
            float2 k01 = unpack2(kk.x), k23 = unpack2(kk.y);
            unsigned long long dk[4] = {pack2(k01.x, k01.x), pack2(k01.y, k01.y),
                                        pack2(k23.x, k23.x), pack2(k23.y, k23.y)};
#pragma unroll
            for (int dj = 0; dj < 4; dj++) { fma2(kvp[dj][0], dk[dj], vv.x); fma2(kvp[dj][1], dk[dj], vv.y); }
        }
    }

    __syncthreads();
    float* kred = &ks[0][0];
#pragma unroll
    for (int dj = 0; dj < 4; dj++)
#pragma unroll
        for (int ep = 0; ep < 2; ep++) {
            float2 v = unpack2(kvp[dj][ep]);
            int entry0 = (hd2 * 16 + d4 + dj) * 16 + e4 + ep * 2;
            kred[entry0 * 4 + q4] = v.x;
            kred[(entry0 + 1) * 4 + q4] = v.y;
        }
    __syncthreads();
    {
        float* pkv = g_part_kv + ((size_t)(b * PB + pb)) * 1024;
#pragma unroll
        for (int k = 0; k < 4; k++) {
            float4 v = *(const float4*)&kred[(tid * 4 + k) * 4];
            pkv[tid * 4 + k] = (v.x + v.y) + (v.z + v.w);
        }
    }
    __syncthreads();
    float* red = &ks[0][0];
#pragma unroll
    for (int j = 0; j < 8; j++) {
        int c = wn * 32 + (j >> 1) * 8 + t4 * 2 + (j & 1);
        red[c * 32 + wm * 8 + g] = ksum8[j];
    }
    __syncthreads();
    if (tid < 64) {
        float s = 0.f;
#pragma unroll
        for (int i = 0; i < 32; i++) s += red[tid * 32 + i];
        g_part_ks[(size_t)(b * PB + pb) * 64 + tid] = s;
    }
}

__global__ __launch_bounds__(256) void reduce_pass() {
    const int b = blockIdx.x, tid = threadIdx.x;
    const float invN = 1.0f / (float)Nn;
    for (int e = tid; e < 1024; e += 256) {
        float s = 0.f;
        for (int p = 0; p < PB; p++) s += g_part_kv[(size_t)(b * PB + p) * 1024 + e];
        g_kvn[b * 1024 + e] = s * invN;
    }
    if (tid < 64) {
        float s = 0.f;
        for (int p = 0; p < PB; p++) s += g_part_ks[(size_t)(b * PB + p) * 64 + tid];
        g_kmean[b * 64 + tid] = s * invN;
    }
}

// ===========================================================================
// q_pass_mma (R14 design + restructured GEMM1 + pre-split W)
// ===========================================================================
#define UA_HI 0
#define UA_LO 2304
#define UB_HI 4608
#define UB_LO 6912
#define FSKV  9216
#define FSKM  10240
#define FSKB  10304
#define SMEM_Q (10368 * 4)
#define AST 66

__global__ __launch_bounds__(256, 4) void q_pass_mma(const float* __restrict__ x,
                                                     const float* __restrict__ qkb,
                                                     const float* __restrict__ lw,
                                                     const float* __restrict__ lb,
                                                     float* __restrict__ out) {
    extern __shared__ float sm[];
    uint32_t* su = (uint32_t*)sm;
    float* abuf  = sm;
    float* slepe = sm + 64 * AST;
    float* skv   = sm + FSKV;
    float* skm   = sm + FSKM;
    float* skb   = sm + FSKB;
    const uint32_t smb = smem_u32(sm);

    const int b = blockIdx.y, tile = blockIdx.x, tid = threadIdx.x;
    const int wid = tid >> 5, lid = tid & 31;
    const int token0 = tile * TT;
    const float* xb = x + (size_t)b * Nn * Cc;

#pragma unroll
    for (int k = 0; k < 4; k++) {
        int idx = tid + k * 256;
        int t = idx >> 4, c4 = idx & 15;
        float4 v = *(const float4*)(xb + (size_t)(token0 + t) * Cc + c4 * 4);
        uint32_t h0, l0, h1, l1;
        bf_split(v.x, v.y, h0, l0);
        bf_split(v.z, v.w, h1, l1);
        int o = t * 36 + c4 * 2;
        *(uint2*)&su[UA_HI + o] = make_uint2(h0, h1);
        *(uint2*)&su[UA_LO + o] = make_uint2(l0, l1);
        *(uint2*)&su[UB_HI + o] = *(const uint2*)&g_wq_hi[t * 32 + c4 * 2];
        *(uint2*)&su[UB_LO + o] = *(const uint2*)&g_wq_lo[t * 32 + c4 * 2];
    }
    for (int i = tid; i < 1024; i += 256) skv[i] = g_kvn[b * 1024 + i];
    if (tid < 64) skm[tid] = g_kmean[b * 64 + tid];
    if (tid >= 64 && tid < 128) skb[tid - 64] = qkb[tid - 64];
    __syncthreads();

    const int g = lid >> 2, t4 = lid & 3;
    const int wm = wid & 3, wn = wid >> 2;
    const int Ml = lid >> 3;
    const uint32_t awordb = (uint32_t)((wm * 16 + (lid & 7) + ((lid >> 3) & 1) * 8) * 36
                                       + ((lid >> 4) & 1) * 4);
    const uint32_t bwordb = (uint32_t)((wn * 32 + (Ml >> 1) * 8 + (lid & 7)) * 36 + (Ml & 1) * 4);

    float acc[4][4] = {};
    GEMM1_BODY(UA_HI, UA_LO, UB_HI, UB_LO)

    uint32_t afh[2][4], afl[2][4];
#pragma unroll
    for (int half = 0; half < 2; half++) {
        int r = wm * 16 + g + half * 8;
        int token = token0 + r;
        float q[8];
        float zp0 = 0.f, zp1 = 0.f;
#pragma unroll
        for (int nt = 0; nt < 4; nt++) {
            int n = wn * 32 + nt * 8 + t4 * 2;
            float q0 = elu1(acc[nt][half * 2 + 0] + skb[n]);
            float q1 = elu1(acc[nt][half * 2 + 1] + skb[n + 1]);
            float zc = q0 * skm[n] + q1 * skm[n + 1];
            if (nt < 2) zp0 += zc; else zp1 += zc;
            q[nt * 2] = q0; q[nt * 2 + 1] = q1;
        }
        zp0 += __shfl_xor_sync(0xffffffffu, zp0, 1);
        zp0 += __shfl_xor_sync(0xffffffffu, zp0, 2);
        zp1 += __shfl_xor_sync(0xffffffffu, zp1, 1);
        zp1 += __shfl_xor_sync(0xffffffffu, zp1, 2);
        float z0 = 1.0f / (zp0 + 1e-6f), z1 = 1.0f / (zp1 + 1e-6f);
        int pos = (wn == 0) ? (token >> 7) : (token & 127);
#pragma unroll
        for (int nt = 0; nt < 4; nt++) {
            float2 cs = __ldg(&g_cs[pos * 16 + nt * 4 + t4]);
            float zz = (nt < 2) ? z0 : z1;
            float ox = (q[2 * nt] * cs.x - q[2 * nt + 1] * cs.y) * zz;
            float oy = (q[2 * nt] * cs.y + q[2 * nt + 1] * cs.x) * zz;
            int hh2 = nt >> 1, slot = (nt & 1) * 2 + half;
            bf_split(ox, oy, afh[hh2][slot], afl[hh2][slot]);
        }
    }
    __syncthreads();

#pragma unroll
    for (int hh2 = 0; hh2 < 2; hh2++) {
        int head = wn * 2 + hh2;
        const float* kvh = skv + head * 256 + g;
#pragma unroll
        for (int nh = 0; nh < 2; nh++) {
            const float* kb = kvh + nh * 8;
            float f00 = kb[(2 * t4) * 16],     f01 = kb[(2 * t4 + 1) * 16];
            float f10 = kb[(2 * t4 + 8) * 16], f11 = kb[(2 * t4 + 9) * 16];
            uint32_t bh0, bl0, bh1, bl1;
            bf_split(f00, f01, bh0, bl0);
            bf_split(f10, f11, bh1, bl1);
            float c[4] = {0.f, 0.f, 0.f, 0.f};
            mma_bf16(c, afh[hh2][0], afh[hh2][1], afh[hh2][2], afh[hh2][3], bh0, bh1);
            mma_bf16(c, afh[hh2][0], afh[hh2][1], afh[hh2][2], afh[hh2][3], bl0, bl1);
            mma_bf16(c, afl[hh2][0], afl[hh2][1], afl[hh2][2], afl[hh2][3], bh0, bh1);
            int col = head * 16 + nh * 8 + 2 * t4;
            int r0 = wm * 16 + g;
            *(float2*)&abuf[r0 * AST + col]       = make_float2(c[0], c[1]);
            *(float2*)&abuf[(r0 + 8) * AST + col] = make_float2(c[2], c[3]);
        }
    }

    {
        int ch = tid & 63, tg = tid >> 6;
        float w9[9];
#pragma unroll
        for (int k = 0; k < 9; k++) w9[k] = lw[ch * 9 + k];
        float biasl = lb[ch];
        const int hh = token0 >> 7;
        const int ww0 = token0 & 127;
        const int wstart = ww0 + tg * 16;
        const bool hm = hh > 0, hp = hh < (Hh - 1);
        const float* rm = xb + ((size_t)(hh - 1) * Ww) * Cc + ch;
        const float* r0p = xb + ((size_t)hh * Ww) * Cc + ch;
        const float* rp = xb + ((size_t)(hh + 1) * Ww) * Cc + ch;
        float La, Lb2, Lc, Ma, Mb2, Mc, Ra, Rb2, Rc;
        {
            int gw = wstart - 1;
            if ((unsigned)gw < (unsigned)Ww) {
                La = hm ? rm[(size_t)gw * Cc] : 0.f;
                Lb2 = r0p[(size_t)gw * Cc];
                Lc = hp ? rp[(size_t)gw * Cc] : 0.f;
            } else { La = Lb2 = Lc = 0.f; }
            gw = wstart;
            Ma = hm ? rm[(size_t)gw * Cc] : 0.f;
            Mb2 = r0p[(size_t)gw * Cc];
            Mc = hp ? rp[(size_t)gw * Cc] : 0.f;
        }
#pragma unroll
        for (int j = 0; j < 16; j++) {
            int gw = wstart + j + 1;
            if ((unsigned)gw < (unsigned)Ww) {
                Ra = hm ? rm[(size_t)gw * Cc] : 0.f;
                Rb2 = r0p[(size_t)gw * Cc];
                Rc = hp ? rp[(size_t)gw * Cc] : 0.f;
            } else { Ra = Rb2 = Rc = 0.f; }
            float s = biasl;
            s = fmaf(w9[0], La, s);  s = fmaf(w9[1], Ma, s);  s = fmaf(w9[2], Ra, s);
            s = fmaf(w9[3], Lb2, s); s = fmaf(w9[4], Mb2, s); s = fmaf(w9[5], Rb2, s);
            s = fmaf(w9[6], Lc, s);  s = fmaf(w9[7], Mc, s);  s = fmaf(w9[8], Rc, s);
            slepe[(tg * 16 + j) * AST + ch] = s;
            La = Ma; Lb2 = Mb2; Lc = Mc;
            Ma = Ra; Mb2 = Rb2; Mc = Rc;
        }
    }
    __syncthreads();

    {
        int t = tid & 63, hg = tid >> 6;
        int token = token0 + t;
        float* ob = out + (size_t)b * Cc * Nn;
#pragma unroll
        for (int j = 0; j < 16; j++) {
            int ch = hg * 16 + j;
            ob[(size_t)ch * Nn + token] = abuf[t * AST + ch] + slepe[t * AST + ch];
        }
    }
}

// ---------------------------------------------------------------------------
extern "C" void kernel_launch(void* const* d_in, const int* in_sizes, int n_in,
                              void* d_out, int out_size) {
    const float* x   = (const float*)d_in[0];
    const float* qkw = (const float*)d_in[3];
    const float* qkb = (const float*)d_in[4];
    const float* lw  = (const float*)d_in[5];
    const float* lb  = (const float*)d_in[6];
    float* out = (float*)d_out;

    int B = in_sizes[0] / (Nn * Cc);
    if (B > BMAX) B = BMAX;

    cudaFuncSetAttribute(k_pass_mma, cudaFuncAttributeMaxDynamicSharedMemorySize, SMEM_K2);
    cudaFuncSetAttribute(q_pass_mma, cudaFuncAttributeMaxDynamicSharedMemorySize, SMEM_Q);

    init_tables<<<8, 256>>>(qkw);
    k_pass_mma<<<dim3(PB, B), 256, SMEM_K2>>>(x, qkb);
    reduce_pass<<<B, 256>>>();
    q_pass_mma<<<dim3(TILES, B), 256, SMEM_Q>>>(x, qkb, lw, lb, out);
}

// round 17
// speedup vs baseline: 1.3549x; 1.1120x over previous
#include <cuda_runtime.h>
#include <cuda_bf16.h>
#include <math.h>
#include <stdint.h>

#define Hh 128
#define Ww 128
#define Nn (Hh*Ww)
#define Cc 64
#define TT 64
#define TILES (Nn/TT)
#define PB 37
#define BMAX 16

__device__ float g_part_kv[BMAX*PB*1024];
__device__ float g_part_ks[BMAX*PB*64];
__device__ float g_kvn[BMAX*1024];
__device__ float g_kmean[BMAX*64];
__device__ float2 g_cs[2048];
__device__ uint32_t g_wq_hi[2048], g_wq_lo[2048], g_wk_hi[2048], g_wk_lo[2048];
__device__ uint4 g_kvb[BMAX*256];   // pre-split kv B-fragments: [b][(head*2+nh)*32+lane]

#define LN1E4_OVER16 0.57564627324851145f

__device__ __forceinline__ float elu1(float v) { return v > 0.f ? v + 1.f : __expf(v); }
__device__ __forceinline__ unsigned long long pack2(float lo, float hi) {
    unsigned long long r; asm("mov.b64 %0, {%1,%2};" : "=l"(r) : "f"(lo), "f"(hi)); return r;
}
__device__ __forceinline__ float2 unpack2(unsigned long long v) {
    float2 r; asm("mov.b64 {%0,%1}, %2;" : "=f"(r.x), "=f"(r.y) : "l"(v)); return r;
}
__device__ __forceinline__ void fma2(unsigned long long& d, unsigned long long a, unsigned long long b) {
    asm("fma.rn.f32x2 %0, %1, %2, %0;" : "+l"(d) : "l"(a), "l"(b));
}
__device__ __forceinline__ void bf_split(float a, float b, uint32_t& hi, uint32_t& lo) {
    __nv_bfloat162 h(__float2bfloat16(a), __float2bfloat16(b));
    hi = *(uint32_t*)&h;
    __nv_bfloat162 l(__float2bfloat16(a - __bfloat162float(h.x)),
                     __float2bfloat16(b - __bfloat162float(h.y)));
    lo = *(uint32_t*)&l;
}
__device__ __forceinline__ void mma_bf16(float* c, uint32_t a0, uint32_t a1, uint32_t a2,
                                         uint32_t a3, uint32_t b0, uint32_t b1) {
    asm volatile("mma.sync.aligned.m16n8k16.row.col.f32.bf16.bf16.f32 "
                 "{%0,%1,%2,%3}, {%4,%5,%6,%7}, {%8,%9}, {%0,%1,%2,%3};"
                 : "+f"(c[0]), "+f"(c[1]), "+f"(c[2]), "+f"(c[3])
                 : "r"(a0), "r"(a1), "r"(a2), "r"(a3), "r"(b0), "r"(b1));
}
__device__ __forceinline__ void ldsm4(uint32_t addr, uint32_t& r0, uint32_t& r1,
                                      uint32_t& r2, uint32_t& r3) {
    asm volatile("ldmatrix.sync.aligned.m8n8.x4.shared.b16 {%0,%1,%2,%3}, [%4];"
                 : "=r"(r0), "=r"(r1), "=r"(r2), "=r"(r3) : "r"(addr));
}
__device__ __forceinline__ uint32_t smem_u32(const void* p) {
    uint32_t a;
    asm("{ .reg .u64 t; cvta.to.shared.u64 t, %1; cvt.u32.u64 %0, t; }" : "=r"(a) : "l"(p));
    return a;
}

__global__ void init_tables(const float* __restrict__ qkw) {
    int idx = threadIdx.x + blockIdx.x * 256;
    if (idx < 2048) {
        int pos = idx >> 4, k = idx & 15;
        float theta = expf(-(float)k * LN1E4_OVER16);
        g_cs[idx] = make_float2(cosf((float)pos * theta), sinf((float)pos * theta));
    }
    if (idx < 1024) {
        int f = idx >> 4, c4 = idx & 15;
        float4 wq = *(const float4*)(qkw + (size_t)f * 64 + c4 * 4);
        float4 wk = *(const float4*)(qkw + (size_t)(64 + f) * 64 + c4 * 4);
        uint32_t h0, l0, h1, l1;
        bf_split(wq.x, wq.y, h0, l0); bf_split(wq.z, wq.w, h1, l1);
        g_wq_hi[f * 32 + c4 * 2] = h0; g_wq_hi[f * 32 + c4 * 2 + 1] = h1;
        g_wq_lo[f * 32 + c4 * 2] = l0; g_wq_lo[f * 32 + c4 * 2 + 1] = l1;
        bf_split(wk.x, wk.y, h0, l0); bf_split(wk.z, wk.w, h1, l1);
        g_wk_hi[f * 32 + c4 * 2] = h0; g_wk_hi[f * 32 + c4 * 2 + 1] = h1;
        g_wk_lo[f * 32 + c4 * 2] = l0; g_wk_lo[f * 32 + c4 * 2 + 1] = l1;
    }
}

// ---- shared GEMM1 macro body: per-kt fused 3-term hi/lo ----
#define GEMM1_BODY(AHI, ALO, BHI, BLO)                                           \
    {                                                                            \
        const uint32_t AoffH = smb + (AHI) * 4, AoffL = smb + (ALO) * 4;         \
        const uint32_t BoffH = smb + (BHI) * 4, BoffL = smb + (BLO) * 4;         \
        _Pragma("unroll")                                                        \
        for (int kt = 0; kt < 4; kt++) {                                         \
            uint32_t ah0, ah1, ah2, ah3, al0, al1, al2, al3;                     \
            ldsm4(AoffH + (awordb + kt * 8) * 4, ah0, ah1, ah2, ah3);            \
            ldsm4(AoffL + (awordb + kt * 8) * 4, al0, al1, al2, al3);            \
            _Pragma("unroll")                                                    \
            for (int p = 0; p < 2; p++) {                                        \
                uint32_t bh00, bh01, bh10, bh11, bl00, bl01, bl10, bl11;         \
                ldsm4(BoffH + (bwordb + p * 16 * 36 + kt * 8) * 4, bh00, bh01, bh10, bh11); \
                ldsm4(BoffL + (bwordb + p * 16 * 36 + kt * 8) * 4, bl00, bl01, bl10, bl11); \
                mma_bf16(acc[2 * p], ah0, ah1, ah2, ah3, bh00, bh01);            \
                mma_bf16(acc[2 * p + 1], ah0, ah1, ah2, ah3, bh10, bh11);        \
                mma_bf16(acc[2 * p], ah0, ah1, ah2, ah3, bl00, bl01);            \
                mma_bf16(acc[2 * p + 1], ah0, ah1, ah2, ah3, bl10, bl11);        \
                mma_bf16(acc[2 * p], al0, al1, al2, al3, bh00, bh01);            \
                mma_bf16(acc[2 * p + 1], al0, al1, al2, al3, bh10, bh11);        \
            }                                                                    \
        }                                                                        \
    }

// ===========================================================================
// k_pass_mma (R16 design, PB=37)
// ===========================================================================
#define KW_HI 0
#define KW_LO 2304
#define KA_HI 4608
#define KA_LO 6912
#define KKS   4608
#define KXS   9216
#define SMEM_K2 (13568 * 4)

__global__ __launch_bounds__(256, 4) void k_pass_mma(const float* __restrict__ x,
                                                     const float* __restrict__ qkb) {
    extern __shared__ float sm[];
    uint32_t* su = (uint32_t*)sm;
    float (*ks)[68] = (float (*)[68])(sm + KKS);
    float (*xs)[68] = (float (*)[68])(sm + KXS);
    const uint32_t smb = smem_u32(sm);

    const int b = blockIdx.y, pb = blockIdx.x, tid = threadIdx.x;
    const int wid = tid >> 5, lid = tid & 31;
    const int g = lid >> 2, t4 = lid & 3;
    const int wm = wid & 3, wn = wid >> 2;
    const float* xb = x + (size_t)b * Nn * Cc;

#pragma unroll
    for (int k = 0; k < 4; k++) {
        int idx = tid + k * 256;
        int f = idx >> 4, c4 = idx & 15;
        int o = f * 36 + c4 * 2;
        *(uint2*)&su[KW_HI + o] = *(const uint2*)&g_wk_hi[f * 32 + c4 * 2];
        *(uint2*)&su[KW_LO + o] = *(const uint2*)&g_wk_lo[f * 32 + c4 * 2];
    }

    float ksum8[8] = {};
    const int e4 = (tid & 3) * 4, d4 = ((tid >> 2) & 3) * 4;
    const int q4 = (tid >> 4) & 3, hd2 = tid >> 6;
    unsigned long long kvp[4][2] = {};
    const int Ml = lid >> 3;
    const uint32_t awordb = (uint32_t)((wm * 16 + (lid & 7) + ((lid >> 3) & 1) * 8) * 36
                                       + ((lid >> 4) & 1) * 4);
    const uint32_t bwordb = (uint32_t)((wn * 32 + (Ml >> 1) * 8 + (lid & 7)) * 36 + (Ml & 1) * 4);

    for (int tile = pb; tile < TILES; tile += PB) {
        const int token0 = tile * TT;
        __syncthreads();
#pragma unroll
        for (int k = 0; k < 4; k++) {
            int idx = tid + k * 256;
            int t = idx >> 4, c4 = idx & 15;
            float4 v = *(const float4*)(xb + (size_t)(token0 + t) * Cc + c4 * 4);
            *(float4*)&xs[t][c4 * 4] = v;
            uint32_t h0, l0, h1, l1;
            bf_split(v.x, v.y, h0, l0);
            bf_split(v.z, v.w, h1, l1);
            int o = t * 36 + c4 * 2;
            *(uint2*)&su[KA_HI + o] = make_uint2(h0, h1);
            *(uint2*)&su[KA_LO + o] = make_uint2(l0, l1);
        }
        __syncthreads();

        float acc[4][4] = {};
        GEMM1_BODY(KA_HI, KA_LO, KW_HI, KW_LO)
        __syncthreads();

#pragma unroll
        for (int half = 0; half < 2; half++) {
            int r = wm * 16 + g + half * 8;
            int token = token0 + r;
            int pos = (wn == 0) ? (token >> 7) : (token & 127);
#pragma unroll
            for (int nt = 0; nt < 4; nt++) {
                int n = wn * 32 + nt * 8 + t4 * 2;
                float k0 = elu1(acc[nt][half * 2 + 0] + __ldg(qkb + 64 + n));
                float k1 = elu1(acc[nt][half * 2 + 1] + __ldg(qkb + 64 + n + 1));
                ksum8[nt * 2] += k0; ksum8[nt * 2 + 1] += k1;
                float2 cs = __ldg(&g_cs[pos * 16 + nt * 4 + t4]);
                float2 o;
                o.x = k0 * cs.x - k1 * cs.y;
                o.y = k0 * cs.y + k1 * cs.x;
                *(float2*)&ks[r][n] = o;
            }
        }
        __syncthreads();

#pragma unroll 4
        for (int t = q4 * 16; t < q4 * 16 + 16; t++) {
            ulonglong2 kk = *(const ulonglong2*)&ks[t][hd2 * 16 + d4];
            ulonglong2 vv = *(const ulonglong2*)&xs[t][hd2 * 16 + e4];
            float2 k01 = unpack2(kk.x), k23 = unpack2(kk.y);
            unsigned long long dk[4] = {pack2(k01.x, k01.x), pack2(k01.y, k01.y),
                                        pack2(k23.x, k23.x), pack2(k23.y, k23.y)};
#pragma unroll
            for (int dj = 0; dj < 4; dj++) { fma2(kvp[dj][0], dk[dj], vv.x); fma2(kvp[dj][1], dk[dj], vv.y); }
        }
    }

    __syncthreads();
    float* kred = &ks[0][0];
#pragma unroll
    for (int dj = 0; dj < 4; dj++)
#pragma unroll
        for (int ep = 0; ep < 2; ep++) {
            float2 v = unpack2(kvp[dj][ep]);
            int entry0 = (hd2 * 16 + d4 + dj) * 16 + e4 + ep * 2;
            kred[entry0 * 4 + q4] = v.x;
            kred[(entry0 + 1) * 4 + q4] = v.y;
        }
    __syncthreads();
    {
        float* pkv = g_part_kv + ((size_t)(b * PB + pb)) * 1024;
#pragma unroll
        for (int k = 0; k < 4; k++) {
            float4 v = *(const float4*)&kred[(tid * 4 + k) * 4];
            pkv[tid * 4 + k] = (v.x + v.y) + (v.z + v.w);
        }
    }
    __syncthreads();
    float* red = &ks[0][0];
#pragma unroll
    for (int j = 0; j < 8; j++) {
        int c = wn * 32 + (j >> 1) * 8 + t4 * 2 + (j & 1);
        red[c * 32 + wm * 8 + g] = ksum8[j];
    }
    __syncthreads();
    if (tid < 64) {
        float s = 0.f;
#pragma unroll
        for (int i = 0; i < 32; i++) s += red[tid * 32 + i];
        g_part_ks[(size_t)(b * PB + pb) * 64 + tid] = s;
    }
}

// ---------------------------------------------------------------------------
// reduce_pass: kv/n, kmean, AND pre-split kv into GEMM2 B-fragments (g_kvb)
// ---------------------------------------------------------------------------
__global__ __launch_bounds__(256) void reduce_pass() {
    const int b = blockIdx.x, tid = threadIdx.x;
    const float invN = 1.0f / (float)Nn;
    for (int e = tid; e < 1024; e += 256) {
        float s = 0.f;
        for (int p = 0; p < PB; p++) s += g_part_kv[(size_t)(b * PB + p) * 1024 + e];
        g_kvn[b * 1024 + e] = s * invN;
    }
    if (tid < 64) {
        float s = 0.f;
        for (int p = 0; p < PB; p++) s += g_part_ks[(size_t)(b * PB + p) * 64 + tid];
        g_kmean[b * 64 + tid] = s * invN;
    }
    __syncthreads();   // all g_kvn writes by this block visible
    {
        int head = tid >> 6, nh = (tid >> 5) & 1, lane = tid & 31;
        int g = lane >> 2, t4 = lane & 3;
        const float* kvh = g_kvn + b * 1024 + head * 256 + g + nh * 8;
        float f00 = kvh[(2 * t4) * 16],     f01 = kvh[(2 * t4 + 1) * 16];
        float f10 = kvh[(2 * t4 + 8) * 16], f11 = kvh[(2 * t4 + 9) * 16];
        uint32_t bh0, bl0, bh1, bl1;
        bf_split(f00, f01, bh0, bl0);
        bf_split(f10, f11, bh1, bl1);
        g_kvb[b * 256 + (head * 2 + nh) * 32 + lane] = make_uint4(bh0, bh1, bl0, bl1);
    }
}

// ===========================================================================
// q_pass_mma (R16 design, skv staging removed; GEMM2 B from g_kvb)
// smem floats: su A/B hi/lo [0,9216) | skm 9216 | skb 9280 | total 9344
// overlays after GEMM1: abuf float 0 (64x66), slepe float 4224 (64x66)
// ===========================================================================
#define UA_HI 0
#define UA_LO 2304
#define UB_HI 4608
#define UB_LO 6912
#define FSKM  9216
#define FSKB  9280
#define SMEM_Q (9344 * 4)
#define AST 66

__global__ __launch_bounds__(256, 4) void q_pass_mma(const float* __restrict__ x,
                                                     const float* __restrict__ qkb,
                                                     const float* __restrict__ lw,
                                                     const float* __restrict__ lb,
                                                     float* __restrict__ out) {
    extern __shared__ float sm[];
    uint32_t* su = (uint32_t*)sm;
    float* abuf  = sm;
    float* slepe = sm + 64 * AST;
    float* skm   = sm + FSKM;
    float* skb   = sm + FSKB;
    const uint32_t smb = smem_u32(sm);

    const int b = blockIdx.y, tile = blockIdx.x, tid = threadIdx.x;
    const int wid = tid >> 5, lid = tid & 31;
    const int token0 = tile * TT;
    const float* xb = x + (size_t)b * Nn * Cc;

#pragma unroll
    for (int k = 0; k < 4; k++) {
        int idx = tid + k * 256;
        int t = idx >> 4, c4 = idx & 15;
        float4 v = *(const float4*)(xb + (size_t)(token0 + t) * Cc + c4 * 4);
        uint32_t h0, l0, h1, l1;
        bf_split(v.x, v.y, h0, l0);
        bf_split(v.z, v.w, h1, l1);
        int o = t * 36 + c4 * 2;
        *(uint2*)&su[UA_HI + o] = make_uint2(h0, h1);
        *(uint2*)&su[UA_LO + o] = make_uint2(l0, l1);
        *(uint2*)&su[UB_HI + o] = *(const uint2*)&g_wq_hi[t * 32 + c4 * 2];
        *(uint2*)&su[UB_LO + o] = *(const uint2*)&g_wq_lo[t * 32 + c4 * 2];
    }
    if (tid < 64) skm[tid] = g_kmean[b * 64 + tid];
    if (tid >= 64 && tid < 128) skb[tid - 64] = qkb[tid - 64];
    __syncthreads();

    const int g = lid >> 2, t4 = lid & 3;
    const int wm = wid & 3, wn = wid >> 2;
    const int Ml = lid >> 3;
    const uint32_t awordb = (uint32_t)((wm * 16 + (lid & 7) + ((lid >> 3) & 1) * 8) * 36
                                       + ((lid >> 4) & 1) * 4);
    const uint32_t bwordb = (uint32_t)((wn * 32 + (Ml >> 1) * 8 + (lid & 7)) * 36 + (Ml & 1) * 4);

    float acc[4][4] = {};
    GEMM1_BODY(UA_HI, UA_LO, UB_HI, UB_LO)

    uint32_t afh[2][4], afl[2][4];
#pragma unroll
    for (int half = 0; half < 2; half++) {
        int r = wm * 16 + g + half * 8;
        int token = token0 + r;
        float q[8];
        float zp0 = 0.f, zp1 = 0.f;
#pragma unroll
        for (int nt = 0; nt < 4; nt++) {
            int n = wn * 32 + nt * 8 + t4 * 2;
            float q0 = elu1(acc[nt][half * 2 + 0] + skb[n]);
            float q1 = elu1(acc[nt][half * 2 + 1] + skb[n + 1]);
            float zc = q0 * skm[n] + q1 * skm[n + 1];
            if (nt < 2) zp0 += zc; else zp1 += zc;
            q[nt * 2] = q0; q[nt * 2 + 1] = q1;
        }
        zp0 += __shfl_xor_sync(0xffffffffu, zp0, 1);
        zp0 += __shfl_xor_sync(0xffffffffu, zp0, 2);
        zp1 += __shfl_xor_sync(0xffffffffu, zp1, 1);
        zp1 += __shfl_xor_sync(0xffffffffu, zp1, 2);
        float z0 = 1.0f / (zp0 + 1e-6f), z1 = 1.0f / (zp1 + 1e-6f);
        int pos = (wn == 0) ? (token >> 7) : (token & 127);
#pragma unroll
        for (int nt = 0; nt < 4; nt++) {
            float2 cs = __ldg(&g_cs[pos * 16 + nt * 4 + t4]);
            float zz = (nt < 2) ? z0 : z1;
            float ox = (q[2 * nt] * cs.x - q[2 * nt + 1] * cs.y) * zz;
            float oy = (q[2 * nt] * cs.y + q[2 * nt + 1] * cs.x) * zz;
            int hh2 = nt >> 1, slot = (nt & 1) * 2 + half;
            bf_split(ox, oy, afh[hh2][slot], afl[hh2][slot]);
        }
    }
    __syncthreads();   // all su reads done -> abuf/slepe overlays safe

    // GEMM2: B-fragments pre-split in gmem (L2-hot)
#pragma unroll
    for (int hh2 = 0; hh2 < 2; hh2++) {
        int head = wn * 2 + hh2;
#pragma unroll
        for (int nh = 0; nh < 2; nh++) {
            uint4 bb = __ldg(&g_kvb[b * 256 + (head * 2 + nh) * 32 + lid]);
            float c[4] = {0.f, 0.f, 0.f, 0.f};
            mma_bf16(c, afh[hh2][0], afh[hh2][1], afh[hh2][2], afh[hh2][3], bb.x, bb.y);
            mma_bf16(c, afh[hh2][0], afh[hh2][1], afh[hh2][2], afh[hh2][3], bb.z, bb.w);
            mma_bf16(c, afl[hh2][0], afl[hh2][1], afl[hh2][2], afl[hh2][3], bb.x, bb.y);
            int col = head * 16 + nh * 8 + 2 * t4;
            int r0 = wm * 16 + g;
            *(float2*)&abuf[r0 * AST + col]       = make_float2(c[0], c[1]);
            *(float2*)&abuf[(r0 + 8) * AST + col] = make_float2(c[2], c[3]);
        }
    }

    // lepe: thread = (ch 64, tg 4), 16 consecutive w each
    {
        int ch = tid & 63, tg = tid >> 6;
        float w9[9];
#pragma unroll
        for (int k = 0; k < 9; k++) w9[k] = lw[ch * 9 + k];
        float biasl = lb[ch];
        const int hh = token0 >> 7;
        const int ww0 = token0 & 127;
        const int wstart = ww0 + tg * 16;
        const bool hm = hh > 0, hp = hh < (Hh - 1);
        const float* rm = xb + ((size_t)(hh - 1) * Ww) * Cc + ch;
        const float* r0p = xb + ((size_t)hh * Ww) * Cc + ch;
        const float* rp = xb + ((size_t)(hh + 1) * Ww) * Cc + ch;
        float La, Lb2, Lc, Ma, Mb2, Mc, Ra, Rb2, Rc;
        {
            int gw = wstart - 1;
            if ((unsigned)gw < (unsigned)Ww) {
                La = hm ? rm[(size_t)gw * Cc] : 0.f;
                Lb2 = r0p[(size_t)gw * Cc];
                Lc = hp ? rp[(size_t)gw * Cc] : 0.f;
            } else { La = Lb2 = Lc = 0.f; }
            gw = wstart;
            Ma = hm ? rm[(size_t)gw * Cc] : 0.f;
            Mb2 = r0p[(size_t)gw * Cc];
            Mc = hp ? rp[(size_t)gw * Cc] : 0.f;
        }
#pragma unroll
        for (int j = 0; j < 16; j++) {
            int gw = wstart + j + 1;
            if ((unsigned)gw < (unsigned)Ww) {
                Ra = hm ? rm[(size_t)gw * Cc] : 0.f;
                Rb2 = r0p[(size_t)gw * Cc];
                Rc = hp ? rp[(size_t)gw * Cc] : 0.f;
            } else { Ra = Rb2 = Rc = 0.f; }
            float s = biasl;
            s = fmaf(w9[0], La, s);  s = fmaf(w9[1], Ma, s);  s = fmaf(w9[2], Ra, s);
            s = fmaf(w9[3], Lb2, s); s = fmaf(w9[4], Mb2, s); s = fmaf(w9[5], Rb2, s);
            s = fmaf(w9[6], Lc, s);  s = fmaf(w9[7], Mc, s);  s = fmaf(w9[8], Rc, s);
            slepe[(tg * 16 + j) * AST + ch] = s;
            La = Ma; Lb2 = Mb2; Lc = Mc;
            Ma = Ra; Mb2 = Rb2; Mc = Rc;
        }
    }
    __syncthreads();

    // final NCHW write
    {
        int t = tid & 63, hg = tid >> 6;
        int token = token0 + t;
        float* ob = out + (size_t)b * Cc * Nn;
#pragma unroll
        for (int j = 0; j < 16; j++) {
            int ch = hg * 16 + j;
            ob[(size_t)ch * Nn + token] = abuf[t * AST + ch] + slepe[t * AST + ch];
        }
    }
}

// ---------------------------------------------------------------------------
extern "C" void kernel_launch(void* const* d_in, const int* in_sizes, int n_in,
                              void* d_out, int out_size) {
    const float* x   = (const float*)d_in[0];
    const float* qkw = (const float*)d_in[3];
    const float* qkb = (const float*)d_in[4];
    const float* lw  = (const float*)d_in[5];
    const float* lb  = (const float*)d_in[6];
    float* out = (float*)d_out;

    int B = in_sizes[0] / (Nn * Cc);
    if (B > BMAX) B = BMAX;

    cudaFuncSetAttribute(k_pass_mma, cudaFuncAttributeMaxDynamicSharedMemorySize, SMEM_K2);
    cudaFuncSetAttribute(q_pass_mma, cudaFuncAttributeMaxDynamicSharedMemorySize, SMEM_Q);

    init_tables<<<8, 256>>>(qkw);
    k_pass_mma<<<dim3(PB, B), 256, SMEM_K2>>>(x, qkb);
    reduce_pass<<<B, 256>>>();
    q_pass_mma<<<dim3(TILES, B), 256, SMEM_Q>>>(x, qkb, lw, lb, out);
}